// round 1
// baseline (speedup 1.0000x reference)
#include <cuda_runtime.h>
#include <cstdint>

#define B_  512
#define M_  16
#define D_  128
#define P_  16
#define T_  4096
#define R_  (B_*M_)      // 8192 rows = B*M
#define TS  128          // output tile (rows x cols)
#define KP  132          // padded smem stride (keeps 16B alignment, avoids conflicts)

typedef unsigned long long ull;

// scratch for new_state [R_, D_] (4 MB) — no allocations allowed, use device global
__device__ float g_ns[R_ * D_];

__device__ __forceinline__ ull pack2(float x) {
    ull r; asm("mov.b64 %0, {%1, %1};" : "=l"(r) : "f"(x)); return r;
}
__device__ __forceinline__ void fma2(ull& d, ull a, ull b) {
    asm("fma.rn.f32x2 %0, %1, %2, %0;" : "+l"(d) : "l"(a), "l"(b));
}
__device__ __forceinline__ float ex2a(float x) {
    float r; asm("ex2.approx.f32 %0, %1;" : "=f"(r) : "f"(x)); return r;
}

// ---------------------------------------------------------------------------
// Kernel 1: new_state[b,m,h] = tanh( sum_d state[b,d]*A[m,d,h] + sum_p phi[b,p]*Bin[m,p,h] )
// grid (16 btiles, 16 m), 128 threads (thread = h), 32 batches per block.
// ---------------------------------------------------------------------------
__global__ __launch_bounds__(128) void ns_kernel(
    const float* __restrict__ phi, const float* __restrict__ state,
    const float* __restrict__ A,   const float* __restrict__ Bin,
    float* __restrict__ tail)
{
    __shared__ float s_s[32][128];
    __shared__ float s_p[32][16];
    const int m  = blockIdx.y;
    const int b0 = blockIdx.x * 32;
    const int h  = threadIdx.x;

    for (int i = h; i < 32 * 128; i += 128) s_s[i >> 7][i & 127] = state[b0 * 128 + i];
    for (int i = h; i < 32 * 16;  i += 128) s_p[i >> 4][i & 15]  = phi[b0 * 16 + i];
    __syncthreads();

    float acc[32];
#pragma unroll
    for (int bb = 0; bb < 32; bb++) acc[bb] = 0.0f;

    const float* Am = A + (size_t)m * D_ * D_ + h;
#pragma unroll 4
    for (int d = 0; d < 128; d++) {
        float a = Am[d * 128];
#pragma unroll
        for (int bb = 0; bb < 32; bb++) acc[bb] = fmaf(s_s[bb][d], a, acc[bb]);
    }
    const float* Bm = Bin + (size_t)m * P_ * D_ + h;
#pragma unroll
    for (int p = 0; p < 16; p++) {
        float bv = Bm[p * 128];
#pragma unroll
        for (int bb = 0; bb < 32; bb++) acc[bb] = fmaf(s_p[bb][p], bv, acc[bb]);
    }

#pragma unroll 4
    for (int bb = 0; bb < 32; bb++) {
        float v = tanhf(acc[bb]);
        int r = (b0 + bb) * M_ + m;
        g_ns[(size_t)r * D_ + h] = v;
        if (tail) tail[(size_t)r * D_ + h] = v;
    }
}

// ---------------------------------------------------------------------------
// Kernel 2: out[r,t] = exp(-max(ssq[r] + tsq[t] - 2*dot(ns[r,:], tj[t,:]), 0))
// 128x128 tile per block, full K=128 in smem (k-major, stride KP=132),
// 256 threads, 8x8 micro-tile per thread via packed f32x2 FMA.
// ---------------------------------------------------------------------------
__global__ __launch_bounds__(256, 1) void sim_kernel(
    const float* __restrict__ tj, float* __restrict__ out)
{
    extern __shared__ float smc[];
    float* sA  = smc;                  // [128][KP] : sA[k*KP + r]
    float* sB  = smc + 128 * KP;       // [128][KP] : sB[k*KP + c]
    float* ssq = smc + 2 * 128 * KP;   // [128]
    float* tsq = ssq + 128;            // [128]

    const int tid = threadIdx.x;
    const int r0  = blockIdx.y * TS;
    const int t0  = blockIdx.x * TS;

    // --- fill both tiles transposed (k-major). Conflict-free STS; global reads
    // are 16B/lane strided (50% sector eff.) but L2-resident, so cheap.
#pragma unroll
    for (int it = 0; it < 16; it++) {
        int idx = tid + 256 * it;        // 0..4095
        int r   = idx & 127;
        int k4  = idx >> 7;              // 0..31
        float4 v = *reinterpret_cast<const float4*>(&g_ns[(size_t)(r0 + r) * 128 + k4 * 4]);
        sA[(k4 * 4 + 0) * KP + r] = v.x;
        sA[(k4 * 4 + 1) * KP + r] = v.y;
        sA[(k4 * 4 + 2) * KP + r] = v.z;
        sA[(k4 * 4 + 3) * KP + r] = v.w;
        float4 w = *reinterpret_cast<const float4*>(&tj[(size_t)(t0 + r) * 128 + k4 * 4]);
        sB[(k4 * 4 + 0) * KP + r] = w.x;
        sB[(k4 * 4 + 1) * KP + r] = w.y;
        sB[(k4 * 4 + 2) * KP + r] = w.z;
        sB[(k4 * 4 + 3) * KP + r] = w.w;
    }
    __syncthreads();

    // --- row/col squared norms from the resident tiles
    if (tid < 128) {
        float s = 0.0f;
#pragma unroll 8
        for (int k = 0; k < 128; k++) { float v = sA[k * KP + tid]; s = fmaf(v, v, s); }
        ssq[tid] = s;
    } else {
        int c = tid - 128;
        float s = 0.0f;
#pragma unroll 8
        for (int k = 0; k < 128; k++) { float v = sB[k * KP + c]; s = fmaf(v, v, s); }
        tsq[c] = s;
    }
    __syncthreads();

    const int tx = tid & 15;   // col group
    const int ty = tid >> 4;   // row group
    const float* aB = sA + ty * 8;
    const float* bB = sB + tx * 8;

    ull acc[8][4];
#pragma unroll
    for (int i = 0; i < 8; i++)
#pragma unroll
        for (int j = 0; j < 4; j++) acc[i][j] = 0ULL;

#pragma unroll 4
    for (int k = 0; k < 128; k++) {
        const float* ak = aB + k * KP;
        const float* bk = bB + k * KP;
        __align__(16) float a[8];
        *reinterpret_cast<float4*>(a)     = *reinterpret_cast<const float4*>(ak);
        *reinterpret_cast<float4*>(a + 4) = *reinterpret_cast<const float4*>(ak + 4);
        ull b0 = *reinterpret_cast<const ull*>(bk);
        ull b1 = *reinterpret_cast<const ull*>(bk + 2);
        ull b2 = *reinterpret_cast<const ull*>(bk + 4);
        ull b3 = *reinterpret_cast<const ull*>(bk + 6);
#pragma unroll
        for (int i = 0; i < 8; i++) {
            ull pa = pack2(a[i]);
            fma2(acc[i][0], pa, b0);
            fma2(acc[i][1], pa, b1);
            fma2(acc[i][2], pa, b2);
            fma2(acc[i][3], pa, b3);
        }
    }

    // --- epilogue: d = ssq + tsq - 2c (clamped >= 0); sim = 2^(-log2e * d)
    // subnormal-correct: for t < -80, compute 2^(t+64) * 2^-64 (FMUL is non-FTZ)
    const float NL2E = -1.4426950408889634f;
    float nsqv[8], ntqv[8];
#pragma unroll
    for (int i = 0; i < 8; i++) nsqv[i] = ssq[ty * 8 + i];
#pragma unroll
    for (int j = 0; j < 8; j++) ntqv[j] = tsq[tx * 8 + j];

#pragma unroll
    for (int i = 0; i < 8; i++) {
        float cr[8];
#pragma unroll
        for (int j2 = 0; j2 < 4; j2++) {
            float c0, c1;
            asm("mov.b64 {%0, %1}, %2;" : "=f"(c0), "=f"(c1) : "l"(acc[i][j2]));
            cr[j2 * 2]     = c0;
            cr[j2 * 2 + 1] = c1;
        }
        __align__(16) float o[8];
#pragma unroll
        for (int j = 0; j < 8; j++) {
            float d = fmaf(-2.0f, cr[j], nsqv[i] + ntqv[j]);
            d = fmaxf(d, 0.0f);
            float t = NL2E * d;
            float tb = t, sc = 1.0f;
            if (t < -80.0f) { tb = t + 64.0f; sc = 5.421010862427522e-20f; } // 2^-64
            o[j] = ex2a(tb) * sc;
        }
        float* orow = out + (size_t)(r0 + ty * 8 + i) * T_ + t0 + tx * 8;
        *reinterpret_cast<float4*>(orow)     = *reinterpret_cast<float4*>(o);
        *reinterpret_cast<float4*>(orow + 4) = *reinterpret_cast<float4*>(o + 4);
    }
}

// ---------------------------------------------------------------------------
extern "C" void kernel_launch(void* const* d_in, const int* in_sizes, int n_in,
                              void* d_out, int out_size) {
    // All five input element-counts are distinct — identify by size, not order.
    const float *phi = nullptr, *state = nullptr, *traj = nullptr, *A = nullptr, *Bin = nullptr;
    for (int i = 0; i < n_in; i++) {
        switch (in_sizes[i]) {
            case B_ * P_:      phi   = (const float*)d_in[i]; break;  // 8192
            case B_ * D_:      state = (const float*)d_in[i]; break;  // 65536
            case T_ * D_:      traj  = (const float*)d_in[i]; break;  // 524288
            case M_ * D_ * D_: A     = (const float*)d_in[i]; break;  // 262144
            case M_ * P_ * D_: Bin   = (const float*)d_in[i]; break;  // 32768
        }
    }
    float* out = (float*)d_out;
    const long long SIMSZ = (long long)R_ * T_;        // 33,554,432
    const long long NSSZ  = (long long)R_ * D_;        // 1,048,576
    float* tail = ((long long)out_size >= SIMSZ + NSSZ) ? out + SIMSZ : nullptr;

    ns_kernel<<<dim3(16, 16), 128>>>(phi, state, A, Bin, tail);

    size_t smemC = (size_t)(2 * 128 * KP + 256) * sizeof(float);  // 136,192 B
    cudaFuncSetAttribute(sim_kernel, cudaFuncAttributeMaxDynamicSharedMemorySize, (int)smemC);
    sim_kernel<<<dim3(T_ / TS, R_ / TS), 256, smemC>>>(traj, out);
}

// round 3
// speedup vs baseline: 2.2673x; 2.2673x over previous
#include <cuda_runtime.h>
#include <cuda_bf16.h>
#include <cstdint>

#define B_  512
#define M_  16
#define D_  128
#define P_  16
#define T_  4096
#define R_  (B_*M_)          // 8192 rows
#define TMT 128              // CTA tile rows
#define TNT 128              // CTA tile cols

// ---- device-global scratch (no allocations allowed) ----
__device__ __nv_bfloat16 g_nsh[R_ * D_];
__device__ __nv_bfloat16 g_nsl[R_ * D_];
__device__ __nv_bfloat16 g_tjh[T_ * D_];
__device__ __nv_bfloat16 g_tjl[T_ * D_];
__device__ float g_ssq[R_];
__device__ float g_tsq[T_];

// ---------------------------------------------------------------- helpers
__device__ __forceinline__ uint32_t smem_u32(const void* p) {
    uint32_t a;
    asm("{ .reg .u64 t; cvta.to.shared.u64 t, %1; cvt.u32.u64 %0, t; }" : "=r"(a) : "l"(p));
    return a;
}
__device__ __forceinline__ float ex2a(float x) {
    float r; asm("ex2.approx.f32 %0, %1;" : "=f"(r) : "f"(x)); return r;
}
__device__ __forceinline__ void cpasync16(uint32_t s, const void* g) {
    asm volatile("cp.async.cg.shared.global [%0], [%1], 16;" :: "r"(s), "l"(g));
}
#define CP_COMMIT() asm volatile("cp.async.commit_group;" ::: "memory")
#define CP_WAIT(n)  asm volatile("cp.async.wait_group %0;" :: "n"(n) : "memory")

__device__ __forceinline__ void ldsm4(uint32_t* r, uint32_t a) {
    asm volatile("ldmatrix.sync.aligned.m8n8.x4.shared.b16 {%0,%1,%2,%3}, [%4];"
        : "=r"(r[0]), "=r"(r[1]), "=r"(r[2]), "=r"(r[3]) : "r"(a));
}
__device__ __forceinline__ void mma_bf16(float* d, const uint32_t* a, const uint32_t* b) {
    asm volatile(
        "mma.sync.aligned.m16n8k16.row.col.f32.bf16.bf16.f32 "
        "{%0,%1,%2,%3}, {%4,%5,%6,%7}, {%8,%9}, {%0,%1,%2,%3};"
        : "+f"(d[0]), "+f"(d[1]), "+f"(d[2]), "+f"(d[3])
        : "r"(a[0]), "r"(a[1]), "r"(a[2]), "r"(a[3]), "r"(b[0]), "r"(b[1]));
}

// ---------------------------------------------------------------------------
// Kernel 1: new_state + bf16 hi/lo split + row norms (ssq) + optional fp32 tail
// ---------------------------------------------------------------------------
__global__ __launch_bounds__(128) void ns_kernel(
    const float* __restrict__ phi, const float* __restrict__ state,
    const float* __restrict__ A,   const float* __restrict__ Bin,
    float* __restrict__ tail)
{
    __shared__ float s_s[32][128];
    __shared__ float s_p[32][16];
    const int m  = blockIdx.y;
    const int b0 = blockIdx.x * 32;
    const int h  = threadIdx.x;

    for (int i = h; i < 32 * 128; i += 128) s_s[i >> 7][i & 127] = state[b0 * 128 + i];
    for (int i = h; i < 32 * 16;  i += 128) s_p[i >> 4][i & 15]  = phi[b0 * 16 + i];
    __syncthreads();

    float acc[32];
#pragma unroll
    for (int bb = 0; bb < 32; bb++) acc[bb] = 0.0f;

    const float* Am = A + (size_t)m * D_ * D_ + h;
#pragma unroll 2
    for (int d0 = 0; d0 < 128; d0 += 4) {
        float a0 = Am[(d0 + 0) * 128], a1 = Am[(d0 + 1) * 128];
        float a2 = Am[(d0 + 2) * 128], a3 = Am[(d0 + 3) * 128];
#pragma unroll
        for (int bb = 0; bb < 32; bb++) {
            float4 sv = *reinterpret_cast<const float4*>(&s_s[bb][d0]);
            acc[bb] = fmaf(sv.x, a0, acc[bb]);
            acc[bb] = fmaf(sv.y, a1, acc[bb]);
            acc[bb] = fmaf(sv.z, a2, acc[bb]);
            acc[bb] = fmaf(sv.w, a3, acc[bb]);
        }
    }
    const float* Bm = Bin + (size_t)m * P_ * D_ + h;
#pragma unroll
    for (int p0 = 0; p0 < 16; p0 += 4) {
        float a0 = Bm[(p0 + 0) * 128], a1 = Bm[(p0 + 1) * 128];
        float a2 = Bm[(p0 + 2) * 128], a3 = Bm[(p0 + 3) * 128];
#pragma unroll
        for (int bb = 0; bb < 32; bb++) {
            float4 sv = *reinterpret_cast<const float4*>(&s_p[bb][p0]);
            acc[bb] = fmaf(sv.x, a0, acc[bb]);
            acc[bb] = fmaf(sv.y, a1, acc[bb]);
            acc[bb] = fmaf(sv.z, a2, acc[bb]);
            acc[bb] = fmaf(sv.w, a3, acc[bb]);
        }
    }

    __syncthreads();          // done reading s_s; reuse for v^2
#pragma unroll 4
    for (int bb = 0; bb < 32; bb++) {
        float v = tanhf(acc[bb]);
        int r = (b0 + bb) * M_ + m;
        __nv_bfloat16 hi = __float2bfloat16_rn(v);
        float lo = v - __bfloat162float(hi);
        g_nsh[(size_t)r * D_ + h] = hi;
        g_nsl[(size_t)r * D_ + h] = __float2bfloat16_rn(lo);
        if (tail) tail[(size_t)r * D_ + h] = v;
        s_s[bb][h] = v * v;
    }
    __syncthreads();
    if (h < 32) {
        const float4* row = reinterpret_cast<const float4*>(s_s[h]);
        float s = 0.0f;
#pragma unroll
        for (int k = 0; k < 32; k++) { float4 v = row[k]; s += v.x + v.y + v.z + v.w; }
        g_ssq[(b0 + h) * M_ + m] = s;
    }
}

// ---------------------------------------------------------------------------
// Kernel 2: trajectory prep — bf16 hi/lo + tsq. One warp per row.
// ---------------------------------------------------------------------------
__global__ __launch_bounds__(256) void tj_prep(const float* __restrict__ tj)
{
    const int row = blockIdx.x * 8 + (threadIdx.x >> 5);
    const int lid = threadIdx.x & 31;
    float4 v = reinterpret_cast<const float4*>(tj)[row * 32 + lid];
    float f[4] = {v.x, v.y, v.z, v.w};
    uint32_t hp[2], lp[2];
#pragma unroll
    for (int j = 0; j < 2; j++) {
        __nv_bfloat16 h0 = __float2bfloat16_rn(f[2 * j]);
        __nv_bfloat16 h1 = __float2bfloat16_rn(f[2 * j + 1]);
        __nv_bfloat16 l0 = __float2bfloat16_rn(f[2 * j] - __bfloat162float(h0));
        __nv_bfloat16 l1 = __float2bfloat16_rn(f[2 * j + 1] - __bfloat162float(h1));
        hp[j] = (uint32_t)__bfloat16_as_ushort(h0) | ((uint32_t)__bfloat16_as_ushort(h1) << 16);
        lp[j] = (uint32_t)__bfloat16_as_ushort(l0) | ((uint32_t)__bfloat16_as_ushort(l1) << 16);
    }
    uint32_t* oh = reinterpret_cast<uint32_t*>(g_tjh) + row * 64 + lid * 2;
    uint32_t* ol = reinterpret_cast<uint32_t*>(g_tjl) + row * 64 + lid * 2;
    oh[0] = hp[0]; oh[1] = hp[1];
    ol[0] = lp[0]; ol[1] = lp[1];

    float s = f[0]*f[0] + f[1]*f[1] + f[2]*f[2] + f[3]*f[3];
#pragma unroll
    for (int o = 16; o > 0; o >>= 1) s += __shfl_xor_sync(0xFFFFFFFFu, s, o);
    if (lid == 0) g_tsq[row] = s;
}

// ---------------------------------------------------------------------------
// Kernel 3: HMMA (mma.sync bf16 hi/lo x3) GEMM + fused RBF epilogue.
// CTA 128x128, K=128 resident, 8 warps (2x4), warp tile 64x32.
// smem: 4 tiles of 128 rows x 256B, XOR-swizzled (chunk ^= row&7).
// ---------------------------------------------------------------------------
#define OFF_AH   0
#define OFF_AL   32768
#define OFF_BH   65536
#define OFF_BL   98304
#define OFF_SSQ  131072
#define OFF_TSQ  131584
#define SMEM_BYTES 132096

__global__ __launch_bounds__(256, 1) void sim_mma_kernel(float* __restrict__ out)
{
    extern __shared__ __align__(1024) char smem[];
    const uint32_t sb = smem_u32(smem);
    const int tid = threadIdx.x;
    const int wid = tid >> 5;
    const int lid = tid & 31;
    const int warp_m = (wid >> 2) * 64;
    const int warp_n = (wid & 3) * 32;
    const int r0 = blockIdx.y * TMT;
    const int t0 = blockIdx.x * TNT;

    const uint4* gAh = reinterpret_cast<const uint4*>(g_nsh) + (size_t)r0 * 16;
    const uint4* gAl = reinterpret_cast<const uint4*>(g_nsl) + (size_t)r0 * 16;
    const uint4* gBh = reinterpret_cast<const uint4*>(g_tjh) + (size_t)t0 * 16;
    const uint4* gBl = reinterpret_cast<const uint4*>(g_tjl) + (size_t)t0 * 16;

    // ---- async tile loads in two k-half commit groups
#pragma unroll
    for (int ph = 0; ph < 2; ph++) {
#pragma unroll
        for (int i2 = 0; i2 < 4; i2++) {
            int i = tid + i2 * 256;             // 0..1023
            int r = i >> 3, g = (i & 7) + ph * 8;
            uint32_t doff = (uint32_t)r * 256u + (((uint32_t)g * 16u) ^ (((uint32_t)r & 7u) << 4));
            cpasync16(sb + OFF_AH + doff, gAh + r * 16 + g);
            cpasync16(sb + OFF_AL + doff, gAl + r * 16 + g);
            cpasync16(sb + OFF_BH + doff, gBh + r * 16 + g);
            cpasync16(sb + OFF_BL + doff, gBl + r * 16 + g);
        }
        CP_COMMIT();
    }

    // norms into smem
    if (tid < 128) reinterpret_cast<float*>(smem + OFF_SSQ)[tid] = g_ssq[r0 + tid];
    else           reinterpret_cast<float*>(smem + OFF_TSQ)[tid - 128] = g_tsq[t0 + tid - 128];

    float d[4][4][4];
#pragma unroll
    for (int a = 0; a < 4; a++)
#pragma unroll
        for (int b = 0; b < 4; b++)
#pragma unroll
            for (int c = 0; c < 4; c++) d[a][b][c] = 0.0f;

    // per-lane ldmatrix addressing
    const uint32_t xm   = ((uint32_t)lid & 7u) << 4;
    const uint32_t aSel = (lid & 16) ? 16u : 0u;
    const uint32_t bSel = (lid & 8)  ? 16u : 0u;
    uint32_t aBase[4], bBase[2];
#pragma unroll
    for (int mt = 0; mt < 4; mt++)
        aBase[mt] = sb + OFF_AH + (uint32_t)(warp_m + mt * 16 + (lid & 15)) * 256u;
#pragma unroll
    for (int np = 0; np < 2; np++)
        bBase[np] = sb + OFF_BH + (uint32_t)(warp_n + np * 16 + ((lid & 16) >> 1) + (lid & 7)) * 256u;

    CP_WAIT(1);
    __syncthreads();

#pragma unroll
    for (int half = 0; half < 2; half++) {
        if (half == 1) { CP_WAIT(0); __syncthreads(); }
#pragma unroll
        for (int kss = 0; kss < 4; kss++) {
            const int ks = half * 4 + kss;
            const uint32_t koA = ((uint32_t)ks * 32u + aSel) ^ xm;
            const uint32_t koB = ((uint32_t)ks * 32u + bSel) ^ xm;
            uint32_t ah[4][4], al[4][4], bqh[2][4], bql[2][4];
#pragma unroll
            for (int mt = 0; mt < 4; mt++) {
                ldsm4(ah[mt], aBase[mt] + koA);
                ldsm4(al[mt], aBase[mt] + 32768u + koA);
            }
#pragma unroll
            for (int np = 0; np < 2; np++) {
                ldsm4(bqh[np], bBase[np] + koB);
                ldsm4(bql[np], bBase[np] + 32768u + koB);
            }
#pragma unroll
            for (int mt = 0; mt < 4; mt++) {
#pragma unroll
                for (int nt = 0; nt < 4; nt++) {
                    const uint32_t* bh = &bqh[nt >> 1][(nt & 1) * 2];
                    const uint32_t* bl = &bql[nt >> 1][(nt & 1) * 2];
                    mma_bf16(d[mt][nt], ah[mt], bh);
                    mma_bf16(d[mt][nt], ah[mt], bl);
                    mma_bf16(d[mt][nt], al[mt], bh);
                }
            }
        }
    }

    // ---- fused RBF epilogue from accumulator registers
    const float* s_ssq = reinterpret_cast<const float*>(smem + OFF_SSQ);
    const float* s_tsq = reinterpret_cast<const float*>(smem + OFF_TSQ);
    const float NL2E = -1.4426950408889634f;
    const float SC64 = 5.421010862427522e-20f;   // 2^-64

#pragma unroll
    for (int mt = 0; mt < 4; mt++) {
        const int lr = warp_m + mt * 16 + (lid >> 2);
        const float sq0 = s_ssq[lr];
        const float sq1 = s_ssq[lr + 8];
        float* row0 = out + (size_t)(r0 + lr) * T_ + t0;
        float* row1 = row0 + (size_t)8 * T_;
#pragma unroll
        for (int nt = 0; nt < 4; nt++) {
            const int lc = warp_n + nt * 8 + (lid & 3) * 2;
            const float tq0 = s_tsq[lc], tq1 = s_tsq[lc + 1];
            float in[4] = { sq0 + tq0, sq0 + tq1, sq1 + tq0, sq1 + tq1 };
            float o[4];
#pragma unroll
            for (int j = 0; j < 4; j++) {
                float dd = fmaf(-2.0f, d[mt][nt][j], in[j]);
                dd = fmaxf(dd, 0.0f);
                float t = NL2E * dd;
                float tb = t, sc = 1.0f;
                if (t < -80.0f) { tb = t + 64.0f; sc = SC64; }
                o[j] = ex2a(tb) * sc;
            }
            *reinterpret_cast<float2*>(row0 + lc) = make_float2(o[0], o[1]);
            *reinterpret_cast<float2*>(row1 + lc) = make_float2(o[2], o[3]);
        }
    }
}

// ---------------------------------------------------------------------------
extern "C" void kernel_launch(void* const* d_in, const int* in_sizes, int n_in,
                              void* d_out, int out_size) {
    const float *phi = nullptr, *state = nullptr, *traj = nullptr, *A = nullptr, *Bin = nullptr;
    for (int i = 0; i < n_in; i++) {
        switch (in_sizes[i]) {
            case B_ * P_:      phi   = (const float*)d_in[i]; break;  // 8192
            case B_ * D_:      state = (const float*)d_in[i]; break;  // 65536
            case T_ * D_:      traj  = (const float*)d_in[i]; break;  // 524288
            case M_ * D_ * D_: A     = (const float*)d_in[i]; break;  // 262144
            case M_ * P_ * D_: Bin   = (const float*)d_in[i]; break;  // 32768
        }
    }
    float* out = (float*)d_out;
    const long long SIMSZ = (long long)R_ * T_;
    const long long NSSZ  = (long long)R_ * D_;
    float* tail = ((long long)out_size >= SIMSZ + NSSZ) ? out + SIMSZ : nullptr;

    tj_prep<<<T_ / 8, 256>>>(traj);
    ns_kernel<<<dim3(16, 16), 128>>>(phi, state, A, Bin, tail);

    cudaFuncSetAttribute(sim_mma_kernel, cudaFuncAttributeMaxDynamicSharedMemorySize, SMEM_BYTES);
    sim_mma_kernel<<<dim3(T_ / TNT, R_ / TMT), 256, SMEM_BYTES>>>(out);
}

// round 4
// speedup vs baseline: 2.2736x; 1.0028x over previous
#include <cuda_runtime.h>
#include <cuda_bf16.h>
#include <cstdint>

#define B_  512
#define M_  16
#define D_  128
#define P_  16
#define T_  4096
#define R_  (B_*M_)          // 8192 rows
#define TMT 128              // CTA tile rows
#define TNT 128              // CTA tile cols

// ---- device-global scratch (no allocations allowed) ----
__device__ __nv_bfloat16 g_nsh[R_ * D_];
__device__ __nv_bfloat16 g_nsl[R_ * D_];
__device__ __nv_bfloat16 g_tjh[T_ * D_];
__device__ __nv_bfloat16 g_tjl[T_ * D_];
__device__ float g_ssq[R_];
__device__ float g_tsq[T_];

// ---------------------------------------------------------------- helpers
__device__ __forceinline__ uint32_t smem_u32(const void* p) {
    uint32_t a;
    asm("{ .reg .u64 t; cvta.to.shared.u64 t, %1; cvt.u32.u64 %0, t; }" : "=r"(a) : "l"(p));
    return a;
}
__device__ __forceinline__ float ex2a(float x) {
    float r; asm("ex2.approx.f32 %0, %1;" : "=f"(r) : "f"(x)); return r;
}
__device__ __forceinline__ void cpasync16(uint32_t s, const void* g) {
    asm volatile("cp.async.cg.shared.global [%0], [%1], 16;" :: "r"(s), "l"(g));
}
#define CP_COMMIT() asm volatile("cp.async.commit_group;" ::: "memory")
#define CP_WAIT(n)  asm volatile("cp.async.wait_group %0;" :: "n"(n) : "memory")

__device__ __forceinline__ void ldsm4(uint32_t* r, uint32_t a) {
    asm volatile("ldmatrix.sync.aligned.m8n8.x4.shared.b16 {%0,%1,%2,%3}, [%4];"
        : "=r"(r[0]), "=r"(r[1]), "=r"(r[2]), "=r"(r[3]) : "r"(a));
}
__device__ __forceinline__ void mma_bf16(float* d, const uint32_t* a, const uint32_t* b) {
    asm volatile(
        "mma.sync.aligned.m16n8k16.row.col.f32.bf16.bf16.f32 "
        "{%0,%1,%2,%3}, {%4,%5,%6,%7}, {%8,%9}, {%0,%1,%2,%3};"
        : "+f"(d[0]), "+f"(d[1]), "+f"(d[2]), "+f"(d[3])
        : "r"(a[0]), "r"(a[1]), "r"(a[2]), "r"(a[3]), "r"(b[0]), "r"(b[1]));
}

// ---------------------------------------------------------------------------
// Kernel 1 (fused): blockIdx.x < 16  -> new_state + hi/lo split + ssq (+tail)
//                   blockIdx.x >= 16 -> trajectory hi/lo split + tsq
// grid dim3(32, 16), 128 threads.
// ---------------------------------------------------------------------------
__global__ __launch_bounds__(128) void prep_kernel(
    const float* __restrict__ phi, const float* __restrict__ state,
    const float* __restrict__ A,   const float* __restrict__ Bin,
    const float* __restrict__ tj,  float* __restrict__ tail)
{
    if (blockIdx.x >= 16) {
        // ---- trajectory part: 256 logical blocks, 16 rows each, 4 warps
        const int blk = blockIdx.y * 16 + (blockIdx.x - 16);
        const int wrp = threadIdx.x >> 5;
        const int lid = threadIdx.x & 31;
#pragma unroll
        for (int rr = 0; rr < 4; rr++) {
            const int row = blk * 16 + wrp * 4 + rr;
            float4 v = reinterpret_cast<const float4*>(tj)[row * 32 + lid];
            float f[4] = {v.x, v.y, v.z, v.w};
            uint32_t hp[2], lp[2];
#pragma unroll
            for (int j = 0; j < 2; j++) {
                __nv_bfloat16 h0 = __float2bfloat16_rn(f[2 * j]);
                __nv_bfloat16 h1 = __float2bfloat16_rn(f[2 * j + 1]);
                __nv_bfloat16 l0 = __float2bfloat16_rn(f[2 * j] - __bfloat162float(h0));
                __nv_bfloat16 l1 = __float2bfloat16_rn(f[2 * j + 1] - __bfloat162float(h1));
                hp[j] = (uint32_t)__bfloat16_as_ushort(h0) | ((uint32_t)__bfloat16_as_ushort(h1) << 16);
                lp[j] = (uint32_t)__bfloat16_as_ushort(l0) | ((uint32_t)__bfloat16_as_ushort(l1) << 16);
            }
            uint32_t* oh = reinterpret_cast<uint32_t*>(g_tjh) + row * 64 + lid * 2;
            uint32_t* ol = reinterpret_cast<uint32_t*>(g_tjl) + row * 64 + lid * 2;
            oh[0] = hp[0]; oh[1] = hp[1];
            ol[0] = lp[0]; ol[1] = lp[1];
            float s = f[0]*f[0] + f[1]*f[1] + f[2]*f[2] + f[3]*f[3];
#pragma unroll
            for (int o = 16; o > 0; o >>= 1) s += __shfl_xor_sync(0xFFFFFFFFu, s, o);
            if (lid == 0) g_tsq[row] = s;
        }
        return;
    }

    // ---- new_state part
    __shared__ float s_s[32][128];
    __shared__ float s_p[32][16];
    const int m  = blockIdx.y;
    const int b0 = blockIdx.x * 32;
    const int h  = threadIdx.x;

    for (int i = h; i < 32 * 128; i += 128) s_s[i >> 7][i & 127] = state[b0 * 128 + i];
    for (int i = h; i < 32 * 16;  i += 128) s_p[i >> 4][i & 15]  = phi[b0 * 16 + i];
    __syncthreads();

    float acc[32];
#pragma unroll
    for (int bb = 0; bb < 32; bb++) acc[bb] = 0.0f;

    const float* Am = A + (size_t)m * D_ * D_ + h;
#pragma unroll 2
    for (int d0 = 0; d0 < 128; d0 += 4) {
        float a0 = Am[(d0 + 0) * 128], a1 = Am[(d0 + 1) * 128];
        float a2 = Am[(d0 + 2) * 128], a3 = Am[(d0 + 3) * 128];
#pragma unroll
        for (int bb = 0; bb < 32; bb++) {
            float4 sv = *reinterpret_cast<const float4*>(&s_s[bb][d0]);
            acc[bb] = fmaf(sv.x, a0, acc[bb]);
            acc[bb] = fmaf(sv.y, a1, acc[bb]);
            acc[bb] = fmaf(sv.z, a2, acc[bb]);
            acc[bb] = fmaf(sv.w, a3, acc[bb]);
        }
    }
    const float* Bm = Bin + (size_t)m * P_ * D_ + h;
#pragma unroll
    for (int p0 = 0; p0 < 16; p0 += 4) {
        float a0 = Bm[(p0 + 0) * 128], a1 = Bm[(p0 + 1) * 128];
        float a2 = Bm[(p0 + 2) * 128], a3 = Bm[(p0 + 3) * 128];
#pragma unroll
        for (int bb = 0; bb < 32; bb++) {
            float4 sv = *reinterpret_cast<const float4*>(&s_p[bb][p0]);
            acc[bb] = fmaf(sv.x, a0, acc[bb]);
            acc[bb] = fmaf(sv.y, a1, acc[bb]);
            acc[bb] = fmaf(sv.z, a2, acc[bb]);
            acc[bb] = fmaf(sv.w, a3, acc[bb]);
        }
    }

    __syncthreads();          // done reading s_s; reuse for v^2
#pragma unroll 4
    for (int bb = 0; bb < 32; bb++) {
        float v = tanhf(acc[bb]);
        int r = (b0 + bb) * M_ + m;
        __nv_bfloat16 hi = __float2bfloat16_rn(v);
        float lo = v - __bfloat162float(hi);
        g_nsh[(size_t)r * D_ + h] = hi;
        g_nsl[(size_t)r * D_ + h] = __float2bfloat16_rn(lo);
        if (tail) tail[(size_t)r * D_ + h] = v;
        s_s[bb][h] = v * v;
    }
    __syncthreads();
    if (h < 32) {
        const float4* row = reinterpret_cast<const float4*>(s_s[h]);
        float s = 0.0f;
#pragma unroll
        for (int k = 0; k < 32; k++) { float4 v = row[k]; s += v.x + v.y + v.z + v.w; }
        g_ssq[(b0 + h) * M_ + m] = s;
    }
}

// ---------------------------------------------------------------------------
// Kernel 2: HMMA (bf16 hi/lo x3) GEMM + fused RBF epilogue.
// CTA 128x128, 8 warps, warp tile 64x32.
// 3-stage cp.async pipeline over k-chunks of 32 (4 chunks).
// Stage = 4 tiles (Ah, Al, Bh, Bl) x (128 rows x 64B) = 32KB. 96KB total
// -> 2 CTAs/SM. Swizzle: slot = c ^ (r&3) ^ (((r>>2)&1)<<1), conflict-free
// across any 8 consecutive ldmatrix rows.
// ---------------------------------------------------------------------------
#define STG_STRIDE 32768
#define TILE_STRIDE 8192
#define OFF_SSQ  98304
#define OFF_TSQ  98816
#define SMEM_BYTES 99328

__global__ __launch_bounds__(256, 2) void sim_mma_kernel(float* __restrict__ out)
{
    extern __shared__ __align__(1024) char smem[];
    const uint32_t sb = smem_u32(smem);
    const int tid = threadIdx.x;
    const int wid = tid >> 5;
    const int lid = tid & 31;
    const int warp_m = (wid >> 2) * 64;
    const int warp_n = (wid & 3) * 32;
    const int r0 = blockIdx.y * TMT;
    const int t0 = blockIdx.x * TNT;

    const __nv_bfloat16* srcs[4] = {
        g_nsh + (size_t)r0 * D_, g_nsl + (size_t)r0 * D_,
        g_tjh + (size_t)t0 * D_, g_tjl + (size_t)t0 * D_ };

    // fill one stage (k-chunk st in 0..3 -> slot st%3): 8 x 16B per thread
    auto fill = [&](int st) {
        const uint32_t sbase = sb + (uint32_t)(st % 3) * STG_STRIDE;
#pragma unroll
        for (int t = 0; t < 8; t++) {
            const int tile = t >> 1;
            const int rem  = ((t & 1) << 8) + tid;     // 0..511
            const int r = rem >> 2, c = rem & 3;
            const uint32_t slot = (uint32_t)(c ^ (r & 3) ^ (((r >> 2) & 1) << 1));
            const uint32_t dst = sbase + (uint32_t)tile * TILE_STRIDE
                               + (uint32_t)r * 64u + (slot << 4);
            cpasync16(dst, srcs[tile] + r * D_ + st * 32 + c * 8);
        }
    };

    // norms into smem (regular loads, before pipeline)
    if (tid < 128) reinterpret_cast<float*>(smem + OFF_SSQ)[tid] = g_ssq[r0 + tid];
    else           reinterpret_cast<float*>(smem + OFF_TSQ)[tid - 128] = g_tsq[t0 + tid - 128];

    fill(0); CP_COMMIT();
    fill(1); CP_COMMIT();
    fill(2); CP_COMMIT();

    float d[4][4][4];
#pragma unroll
    for (int a = 0; a < 4; a++)
#pragma unroll
        for (int b = 0; b < 4; b++)
#pragma unroll
            for (int c = 0; c < 4; c++) d[a][b][c] = 0.0f;

    // per-lane ldmatrix row addressing
    uint32_t rowOffA[4], rowOffB[2];
    uint32_t rxA, rxB;
    {
        const int ra = warp_m + (lid & 15);     // + mt*16
        rxA = (uint32_t)((ra & 3) ^ (((ra >> 2) & 1) << 1));
#pragma unroll
        for (int mt = 0; mt < 4; mt++) {
            const int r = ra + mt * 16;
            rowOffA[mt] = (uint32_t)r * 64u;
            // (r&3) invariant under +16; ((r>>2)&1) also invariant under +16
        }
        const int rb = warp_n + ((lid & 16) >> 1) + (lid & 7);   // + np*16
        rxB = (uint32_t)((rb & 3) ^ (((rb >> 2) & 1) << 1));
#pragma unroll
        for (int np = 0; np < 2; np++) rowOffB[np] = (uint32_t)(rb + np * 16) * 64u;
    }
    const uint32_t aSel = (lid >> 4) & 1;   // 16B half within 32B k-step
    const uint32_t bSel = (lid >> 3) & 1;

#pragma unroll
    for (int st = 0; st < 4; st++) {
        CP_WAIT(2);
        __syncthreads();
        const uint32_t sbs = sb + (uint32_t)(st % 3) * STG_STRIDE;

#pragma unroll
        for (int ks = 0; ks < 2; ks++) {
            const uint32_t cA = (uint32_t)(ks * 2) + aSel;
            const uint32_t cB = (uint32_t)(ks * 2) + bSel;
            uint32_t bqh[2][4], bql[2][4];
#pragma unroll
            for (int np = 0; np < 2; np++) {
                const uint32_t bo = sbs + 2u * TILE_STRIDE + rowOffB[np] + (((cB ^ rxB)) << 4);
                ldsm4(bqh[np], bo);
                ldsm4(bql[np], bo + TILE_STRIDE);
            }
#pragma unroll
            for (int mt = 0; mt < 4; mt++) {
                uint32_t ah[4], al[4];
                const uint32_t ao = sbs + rowOffA[mt] + (((cA ^ rxA)) << 4);
                ldsm4(ah, ao);
                ldsm4(al, ao + TILE_STRIDE);
#pragma unroll
                for (int nt = 0; nt < 4; nt++) {
                    const uint32_t* bh = &bqh[nt >> 1][(nt & 1) * 2];
                    const uint32_t* bl = &bql[nt >> 1][(nt & 1) * 2];
                    mma_bf16(d[mt][nt], ah, bh);
                    mma_bf16(d[mt][nt], ah, bl);
                    mma_bf16(d[mt][nt], al, bh);
                }
            }
        }
        __syncthreads();
        if (st + 3 < 4) fill(st + 3);
        CP_COMMIT();            // real or empty, keeps group count aligned
    }

    // ---- fused RBF epilogue from accumulator registers
    const float* s_ssq = reinterpret_cast<const float*>(smem + OFF_SSQ);
    const float* s_tsq = reinterpret_cast<const float*>(smem + OFF_TSQ);
    const float NL2E = -1.4426950408889634f;
    const float SC64 = 5.421010862427522e-20f;   // 2^-64

#pragma unroll
    for (int mt = 0; mt < 4; mt++) {
        const int lr = warp_m + mt * 16 + (lid >> 2);
        const float sq0 = s_ssq[lr];
        const float sq1 = s_ssq[lr + 8];
        float* row0 = out + (size_t)(r0 + lr) * T_ + t0;
        float* row1 = row0 + (size_t)8 * T_;
#pragma unroll
        for (int nt = 0; nt < 4; nt++) {
            const int lc = warp_n + nt * 8 + (lid & 3) * 2;
            const float tq0 = s_tsq[lc], tq1 = s_tsq[lc + 1];
            float in[4] = { sq0 + tq0, sq0 + tq1, sq1 + tq0, sq1 + tq1 };
            float o[4];
#pragma unroll
            for (int j = 0; j < 4; j++) {
                float dd = fmaf(-2.0f, d[mt][nt][j], in[j]);
                dd = fmaxf(dd, 0.0f);
                float t = NL2E * dd;
                float tb = t, sc = 1.0f;
                if (t < -80.0f) { tb = t + 64.0f; sc = SC64; }
                o[j] = ex2a(tb) * sc;
            }
            *reinterpret_cast<float2*>(row0 + lc) = make_float2(o[0], o[1]);
            *reinterpret_cast<float2*>(row1 + lc) = make_float2(o[2], o[3]);
        }
    }
}

// ---------------------------------------------------------------------------
extern "C" void kernel_launch(void* const* d_in, const int* in_sizes, int n_in,
                              void* d_out, int out_size) {
    const float *phi = nullptr, *state = nullptr, *traj = nullptr, *A = nullptr, *Bin = nullptr;
    for (int i = 0; i < n_in; i++) {
        switch (in_sizes[i]) {
            case B_ * P_:      phi   = (const float*)d_in[i]; break;  // 8192
            case B_ * D_:      state = (const float*)d_in[i]; break;  // 65536
            case T_ * D_:      traj  = (const float*)d_in[i]; break;  // 524288
            case M_ * D_ * D_: A     = (const float*)d_in[i]; break;  // 262144
            case M_ * P_ * D_: Bin   = (const float*)d_in[i]; break;  // 32768
        }
    }
    float* out = (float*)d_out;
    const long long SIMSZ = (long long)R_ * T_;
    const long long NSSZ  = (long long)R_ * D_;
    float* tail = ((long long)out_size >= SIMSZ + NSSZ) ? out + SIMSZ : nullptr;

    prep_kernel<<<dim3(32, 16), 128>>>(phi, state, A, Bin, traj, tail);

    cudaFuncSetAttribute(sim_mma_kernel, cudaFuncAttributeMaxDynamicSharedMemorySize, SMEM_BYTES);
    sim_mma_kernel<<<dim3(T_ / TNT, R_ / TMT), 256, SMEM_BYTES>>>(out);
}